// round 1
// baseline (speedup 1.0000x reference)
#include <cuda_runtime.h>
#include <cstdint>

// Problem constants
#define B 32
#define N 1024
#define D 768
#define K 512
#define M (B * N)   // 32768 flattened tokens

// Scratch: soft-assignment / logits buffer [M, K] = 64 MB (static device alloc, guard-safe)
__device__ float g_S[(size_t)M * K];
__device__ float g_csq[K];

// ---------------------------------------------------------------------------
// Kernel 1: c_sq[k] = sum_d C[k,d]^2
// ---------------------------------------------------------------------------
__global__ void csq_kernel(const float* __restrict__ C) {
    int k = blockIdx.x;
    int t = threadIdx.x;              // 256 threads
    const float* row = C + (size_t)k * D;
    float s = 0.f;
    for (int d = t; d < D; d += 256) {
        float v = row[d];
        s += v * v;
    }
    // warp reduce
    #pragma unroll
    for (int o = 16; o > 0; o >>= 1) s += __shfl_xor_sync(0xffffffffu, s, o);
    __shared__ float red[8];
    if ((t & 31) == 0) red[t >> 5] = s;
    __syncthreads();
    if (t == 0) {
        float tot = 0.f;
        #pragma unroll
        for (int w = 0; w < 8; w++) tot += red[w];
        g_csq[k] = tot;
    }
}

// ---------------------------------------------------------------------------
// Kernel 2: GEMM1 — logits[m,k] = 2 * sum_d X[m,d]*C[k,d] - csq[k]
// X row-major [M,D], C row-major [K,D]  (NT gemm along D)
// Tile: BM=64, BN=64, BK=16; 256 threads; 4x4 per thread.
// ---------------------------------------------------------------------------
#define BM 64
#define BN 64
#define BKC 16
#define LDA 68   // padded leading dim (68*4B = 272B, 16B-aligned rows)

__global__ __launch_bounds__(256) void gemm1_kernel(const float* __restrict__ X,
                                                    const float* __restrict__ C) {
    __shared__ float As[BKC][LDA];
    __shared__ float Bs[BKC][LDA];

    const int bm = blockIdx.y * BM;
    const int bk = blockIdx.x * BN;
    const int tid = threadIdx.x;

    // Load mapping: each thread loads one float4 from each matrix per BK-step
    const int lr = tid >> 2;          // 0..63 (row in tile)
    const int lc = (tid & 3) * 4;     // 0,4,8,12 (col offset within BK)

    const int tx = tid & 15;          // 0..15
    const int ty = tid >> 4;          // 0..15

    float acc[4][4] = {};

    const float* Arow = X + (size_t)(bm + lr) * D + lc;
    const float* Brow = C + (size_t)(bk + lr) * D + lc;

    for (int d0 = 0; d0 < D; d0 += BKC) {
        float4 a = *(const float4*)(Arow + d0);
        float4 b = *(const float4*)(Brow + d0);
        As[lc + 0][lr] = a.x; As[lc + 1][lr] = a.y;
        As[lc + 2][lr] = a.z; As[lc + 3][lr] = a.w;
        Bs[lc + 0][lr] = b.x; Bs[lc + 1][lr] = b.y;
        Bs[lc + 2][lr] = b.z; Bs[lc + 3][lr] = b.w;
        __syncthreads();

        #pragma unroll
        for (int kk = 0; kk < BKC; kk++) {
            float4 ra = *(const float4*)&As[kk][ty * 4];
            float4 rb = *(const float4*)&Bs[kk][tx * 4];
            float va[4] = {ra.x, ra.y, ra.z, ra.w};
            float vb[4] = {rb.x, rb.y, rb.z, rb.w};
            #pragma unroll
            for (int i = 0; i < 4; i++)
                #pragma unroll
                for (int j = 0; j < 4; j++)
                    acc[i][j] = fmaf(va[i], vb[j], acc[i][j]);
        }
        __syncthreads();
    }

    float cs[4];
    #pragma unroll
    for (int j = 0; j < 4; j++) cs[j] = g_csq[bk + tx * 4 + j];

    #pragma unroll
    for (int i = 0; i < 4; i++) {
        size_t row = (size_t)(bm + ty * 4 + i) * K + bk + tx * 4;
        float4 o;
        o.x = 2.f * acc[i][0] - cs[0];
        o.y = 2.f * acc[i][1] - cs[1];
        o.z = 2.f * acc[i][2] - cs[2];
        o.w = 2.f * acc[i][3] - cs[3];
        *(float4*)&g_S[row] = o;
    }
}

// ---------------------------------------------------------------------------
// Kernel 3: row softmax over K=512 (in-place on g_S). One block per row.
// ---------------------------------------------------------------------------
__global__ __launch_bounds__(256) void softmax_kernel() {
    const int row = blockIdx.x;
    float* p = g_S + (size_t)row * K;
    const int t = threadIdx.x;    // 256 threads, 2 elems each

    float v0 = p[t];
    float v1 = p[t + 256];
    float m = fmaxf(v0, v1);
    #pragma unroll
    for (int o = 16; o > 0; o >>= 1) m = fmaxf(m, __shfl_xor_sync(0xffffffffu, m, o));
    __shared__ float red[8];
    __shared__ float bcast;
    if ((t & 31) == 0) red[t >> 5] = m;
    __syncthreads();
    if (t == 0) {
        float mm = red[0];
        #pragma unroll
        for (int w = 1; w < 8; w++) mm = fmaxf(mm, red[w]);
        bcast = mm;
    }
    __syncthreads();
    const float mx = bcast;

    float e0 = __expf(v0 - mx);
    float e1 = __expf(v1 - mx);
    float s = e0 + e1;
    #pragma unroll
    for (int o = 16; o > 0; o >>= 1) s += __shfl_xor_sync(0xffffffffu, s, o);
    if ((t & 31) == 0) red[t >> 5] = s;
    __syncthreads();
    if (t == 0) {
        float ss = 0.f;
        #pragma unroll
        for (int w = 0; w < 8; w++) ss += red[w];
        bcast = 1.0f / ss;
    }
    __syncthreads();
    const float inv = bcast;

    p[t]       = e0 * inv;
    p[t + 256] = e1 * inv;
}

// ---------------------------------------------------------------------------
// Kernel 4: GEMM2 — per batch: out[b,k,d] = sum_n S[b,n,k] * X[b,n,d]
// S[b] is [N,K] row-major (read "transposed": tiles are contiguous as-is).
// Tile: 64(k) x 64(d), chunk 16 over n; 256 threads; 4x4 per thread.
// ---------------------------------------------------------------------------
__global__ __launch_bounds__(256) void gemm2_kernel(const float* __restrict__ X,
                                                    float* __restrict__ out) {
    __shared__ float Ss[16][64];   // [n][k]  — loads & reads both conflict-free
    __shared__ float Xs[16][64];   // [n][d]

    const int b  = blockIdx.z;
    const int k0 = blockIdx.y * 64;
    const int d0 = blockIdx.x * 64;
    const int tid = threadIdx.x;

    const float* Sb = g_S + (size_t)b * N * K;
    const float* Xb = X   + (size_t)b * N * D;

    const int lr = tid >> 4;          // 0..15 (n within chunk)
    const int lc = (tid & 15) * 4;    // 0..60 (col, float4)

    const int tx = tid & 15;
    const int ty = tid >> 4;

    float acc[4][4] = {};

    for (int n0 = 0; n0 < N; n0 += 16) {
        float4 s4 = *(const float4*)(Sb + (size_t)(n0 + lr) * K + k0 + lc);
        float4 x4 = *(const float4*)(Xb + (size_t)(n0 + lr) * D + d0 + lc);
        *(float4*)&Ss[lr][lc] = s4;
        *(float4*)&Xs[lr][lc] = x4;
        __syncthreads();

        #pragma unroll
        for (int nn = 0; nn < 16; nn++) {
            float4 ra = *(const float4*)&Ss[nn][ty * 4];
            float4 rb = *(const float4*)&Xs[nn][tx * 4];
            float va[4] = {ra.x, ra.y, ra.z, ra.w};
            float vb[4] = {rb.x, rb.y, rb.z, rb.w};
            #pragma unroll
            for (int i = 0; i < 4; i++)
                #pragma unroll
                for (int j = 0; j < 4; j++)
                    acc[i][j] = fmaf(va[i], vb[j], acc[i][j]);
        }
        __syncthreads();
    }

    #pragma unroll
    for (int i = 0; i < 4; i++) {
        size_t row = (size_t)b * K * D + (size_t)(k0 + ty * 4 + i) * D + d0 + tx * 4;
        float4 o = {acc[i][0], acc[i][1], acc[i][2], acc[i][3]};
        *(float4*)&out[row] = o;
    }
}

// ---------------------------------------------------------------------------
extern "C" void kernel_launch(void* const* d_in, const int* in_sizes, int n_in,
                              void* d_out, int out_size) {
    const float* X = (const float*)d_in[0];   // [B,N,D]
    const float* C = (const float*)d_in[1];   // [K,D]
    float* out = (float*)d_out;               // [B,K,D]

    csq_kernel<<<K, 256>>>(C);

    dim3 g1(K / BN, M / BM);                  // (8, 512)
    gemm1_kernel<<<g1, 256>>>(X, C);

    softmax_kernel<<<M, 256>>>();             // 32768 rows

    dim3 g2(D / 64, K / 64, B);               // (12, 8, 32)
    gemm2_kernel<<<g2, 256>>>(X, out);
}

// round 4
// speedup vs baseline: 1.6124x; 1.6124x over previous
#include <cuda_runtime.h>
#include <cuda_bf16.h>
#include <cstdint>

// ---------------------------------------------------------------------------
// Problem constants
// ---------------------------------------------------------------------------
static constexpr int Bc = 32;
static constexpr int Nc = 1024;
static constexpr int Dc = 768;
static constexpr int Kc = 512;
static constexpr int Mc = Bc * Nc;   // 32768 tokens

// ---------------------------------------------------------------------------
// Global scratch (static __device__ — allocation-guard safe)
//   g_L   : logits, TRANSPOSED layout [Kc][Mc] fp32            (64 MB)
//   g_St  : softmax probs hi/lo bf16, [Kc][Mc]                 (32+32 MB)
//   g_XT  : X transposed hi/lo bf16, [b][d][n]                 (48+48 MB)
// ---------------------------------------------------------------------------
__device__ __align__(16) float         g_L[(size_t)Kc * Mc];
__device__ float                       g_csq[Kc];
__device__ __align__(16) __nv_bfloat16 g_St_hi[(size_t)Kc * Mc];
__device__ __align__(16) __nv_bfloat16 g_St_lo[(size_t)Kc * Mc];
__device__ __align__(16) __nv_bfloat16 g_XT_hi[(size_t)Bc * Dc * Nc];
__device__ __align__(16) __nv_bfloat16 g_XT_lo[(size_t)Bc * Dc * Nc];

// ---------------------------------------------------------------------------
// mma.sync / ldmatrix primitives (baseline sm_80+ PTX — no 'a'-target needed)
// ---------------------------------------------------------------------------
__device__ __forceinline__ uint32_t smem_u32(const void* p) {
    uint32_t a;
    asm("{ .reg .u64 t; cvta.to.shared.u64 t, %1; cvt.u32.u64 %0, t; }" : "=r"(a) : "l"(p));
    return a;
}

__device__ __forceinline__ void ldsm4(uint32_t (&r)[4], uint32_t addr) {
    asm volatile("ldmatrix.sync.aligned.m8n8.x4.shared.b16 {%0,%1,%2,%3}, [%4];"
                 : "=r"(r[0]), "=r"(r[1]), "=r"(r[2]), "=r"(r[3]) : "r"(addr));
}
__device__ __forceinline__ void ldsm2(uint32_t (&r)[2], uint32_t addr) {
    asm volatile("ldmatrix.sync.aligned.m8n8.x2.shared.b16 {%0,%1}, [%2];"
                 : "=r"(r[0]), "=r"(r[1]) : "r"(addr));
}
__device__ __forceinline__ void mma_bf16(float (&d)[4], const uint32_t (&a)[4],
                                         const uint32_t (&b)[2]) {
    asm volatile(
        "mma.sync.aligned.m16n8k16.row.col.f32.bf16.bf16.f32 "
        "{%0,%1,%2,%3}, {%4,%5,%6,%7}, {%8,%9}, {%0,%1,%2,%3};"
        : "+f"(d[0]), "+f"(d[1]), "+f"(d[2]), "+f"(d[3])
        : "r"(a[0]), "r"(a[1]), "r"(a[2]), "r"(a[3]), "r"(b[0]), "r"(b[1]));
}

// ---------------------------------------------------------------------------
// Shared tile geometry: 128 rows x 32 (bf16) cols, padded row stride 40 elems
// (40*2 = 80 bytes, multiple of 16 -> every ldmatrix row address is aligned)
// ---------------------------------------------------------------------------
static constexpr int TP = 40;
static constexpr int TILE_ELEMS = 128 * TP;   // 5120 elems = 10240 B

// fp32x4 -> (hi,lo) bf16x4 split, store 8B each
__device__ __forceinline__ void cvt_split_store(__nv_bfloat16* hi, __nv_bfloat16* lo,
                                                int eoff, float4 a) {
    float x[4] = {a.x, a.y, a.z, a.w};
    uint32_t hb[4], lb[4];
    #pragma unroll
    for (int i = 0; i < 4; i++) {
        __nv_bfloat16 h = __float2bfloat16(x[i]);
        float r = x[i] - __bfloat162float(h);
        __nv_bfloat16 l = __float2bfloat16(r);
        hb[i] = (uint32_t)__bfloat16_as_ushort(h);
        lb[i] = (uint32_t)__bfloat16_as_ushort(l);
    }
    *(uint2*)(hi + eoff) = make_uint2(hb[0] | (hb[1] << 16), hb[2] | (hb[3] << 16));
    *(uint2*)(lo + eoff) = make_uint2(lb[0] | (lb[1] << 16), lb[2] | (lb[3] << 16));
}

// ---------------------------------------------------------------------------
// Kernel 1: c_sq[k] = sum_d C[k,d]^2
// ---------------------------------------------------------------------------
__global__ void csq_kernel(const float* __restrict__ C) {
    int k = blockIdx.x, t = threadIdx.x;
    const float* row = C + (size_t)k * Dc;
    float s = 0.f;
    for (int d = t; d < Dc; d += 256) { float v = row[d]; s += v * v; }
    #pragma unroll
    for (int o = 16; o > 0; o >>= 1) s += __shfl_xor_sync(0xffffffffu, s, o);
    __shared__ float red[8];
    if ((t & 31) == 0) red[t >> 5] = s;
    __syncthreads();
    if (t == 0) {
        float tot = 0.f;
        #pragma unroll
        for (int w = 0; w < 8; w++) tot += red[w];
        g_csq[k] = tot;
    }
}

// ---------------------------------------------------------------------------
// Kernel 2: convert+transpose X [b][n][d] fp32 -> XT hi/lo bf16 [b][d][n]
// ---------------------------------------------------------------------------
__global__ __launch_bounds__(256) void convX_kernel(const float* __restrict__ X) {
    __shared__ float tile[32][33];
    const int b = blockIdx.z, d0 = blockIdx.x * 32, n0 = blockIdx.y * 32;
    const int tx = threadIdx.x, ty = threadIdx.y;   // (32, 8)
    const float* Xb = X + (size_t)b * Nc * Dc;
    #pragma unroll
    for (int i = 0; i < 4; i++) {
        int r = ty + 8 * i;
        tile[r][tx] = Xb[(size_t)(n0 + r) * Dc + d0 + tx];
    }
    __syncthreads();
    __nv_bfloat16* Hb = g_XT_hi + (size_t)b * Dc * Nc;
    __nv_bfloat16* Lb = g_XT_lo + (size_t)b * Dc * Nc;
    #pragma unroll
    for (int i = 0; i < 4; i++) {
        int rr = ty + 8 * i;
        float v = tile[tx][rr];
        __nv_bfloat16 h = __float2bfloat16(v);
        __nv_bfloat16 l = __float2bfloat16(v - __bfloat162float(h));
        size_t o = (size_t)(d0 + rr) * Nc + n0 + tx;
        Hb[o] = h;
        Lb[o] = l;
    }
}

// ---------------------------------------------------------------------------
// Kernel 3: GEMM1 — Lt[k][m] = 2*<C_k, X_m> - csq[k]   (transposed logits)
// CTA tile 128(k) x 128(m), d-chunks of 32, 8 warps, warp tile 64x32.
// ---------------------------------------------------------------------------
__global__ __launch_bounds__(256) void gemm1_mma(const float* __restrict__ X,
                                                 const float* __restrict__ C) {
    __shared__ __align__(16) __nv_bfloat16 sm[4 * TILE_ELEMS];
    __nv_bfloat16* sAh = sm;
    __nv_bfloat16* sAl = sm + TILE_ELEMS;
    __nv_bfloat16* sBh = sm + 2 * TILE_ELEMS;
    __nv_bfloat16* sBl = sm + 3 * TILE_ELEMS;

    const int tid = threadIdx.x;
    const int wid = tid >> 5, lane = tid & 31;
    const int k0 = blockIdx.x * 128;
    const int m0 = blockIdx.y * 128;
    const int wm = (wid & 1) * 64;
    const int wn = (wid >> 1) * 32;

    const uint32_t uAh = smem_u32(sAh), uAl = smem_u32(sAl);
    const uint32_t uBh = smem_u32(sBh), uBl = smem_u32(sBl);

    const int a_r = lane & 15;
    const int a_c = (lane & 16) ? 8 : 0;
    const int b_r = lane & 7;
    const int b_c = (lane & 8) ? 8 : 0;
    const uint32_t aoff = (uint32_t)((wm + a_r) * TP + a_c) * 2;
    const uint32_t boff = (uint32_t)((wn + b_r) * TP + b_c) * 2;

    const int lrow = tid >> 3, lv = (tid & 7) * 4;  // 128 rows x 32 cols via float4

    float acc[4][4][4] = {};
    float4 pa[4], pb[4];

    #pragma unroll
    for (int i = 0; i < 4; i++) {
        int row = lrow + 32 * i;
        pa[i] = *(const float4*)(C + (size_t)(k0 + row) * Dc + lv);
        pb[i] = *(const float4*)(X + (size_t)(m0 + row) * Dc + lv);
    }

    for (int c = 0; c < Dc / 32; c++) {
        #pragma unroll
        for (int i = 0; i < 4; i++) {
            int row = lrow + 32 * i;
            cvt_split_store(sAh, sAl, row * TP + lv, pa[i]);
            cvt_split_store(sBh, sBl, row * TP + lv, pb[i]);
        }
        __syncthreads();

        if (c + 1 < Dc / 32) {
            int dn = (c + 1) * 32 + lv;
            #pragma unroll
            for (int i = 0; i < 4; i++) {
                int row = lrow + 32 * i;
                pa[i] = *(const float4*)(C + (size_t)(k0 + row) * Dc + dn);
                pb[i] = *(const float4*)(X + (size_t)(m0 + row) * Dc + dn);
            }
        }

        #pragma unroll
        for (int ks = 0; ks < 2; ks++) {
            uint32_t ah[4][4], al[4][4], bh[4][2], bl[4][2];
            #pragma unroll
            for (int mi = 0; mi < 4; mi++) {
                uint32_t off = aoff + (uint32_t)(mi * 16 * TP + ks * 16) * 2;
                ldsm4(ah[mi], uAh + off);
                ldsm4(al[mi], uAl + off);
            }
            #pragma unroll
            for (int ni = 0; ni < 4; ni++) {
                uint32_t off = boff + (uint32_t)(ni * 8 * TP + ks * 16) * 2;
                ldsm2(bh[ni], uBh + off);
                ldsm2(bl[ni], uBl + off);
            }
            #pragma unroll
            for (int mi = 0; mi < 4; mi++)
                #pragma unroll
                for (int ni = 0; ni < 4; ni++) {
                    mma_bf16(acc[mi][ni], ah[mi], bh[ni]);
                    mma_bf16(acc[mi][ni], ah[mi], bl[ni]);
                    mma_bf16(acc[mi][ni], al[mi], bh[ni]);
                }
        }
        __syncthreads();
    }

    #pragma unroll
    for (int mi = 0; mi < 4; mi++) {
        const int kr = k0 + wm + mi * 16 + (lane >> 2);
        const float cs0 = g_csq[kr], cs1 = g_csq[kr + 8];
        #pragma unroll
        for (int ni = 0; ni < 4; ni++) {
            const int mc = m0 + wn + ni * 8 + (lane & 3) * 2;
            float2 o0 = {2.f * acc[mi][ni][0] - cs0, 2.f * acc[mi][ni][1] - cs0};
            float2 o1 = {2.f * acc[mi][ni][2] - cs1, 2.f * acc[mi][ni][3] - cs1};
            *(float2*)(g_L + (size_t)kr * Mc + mc) = o0;
            *(float2*)(g_L + (size_t)(kr + 8) * Mc + mc) = o1;
        }
    }
}

// ---------------------------------------------------------------------------
// Kernel 4: column softmax over k (Lt is [Kc][Mc]) -> St hi/lo bf16
// ---------------------------------------------------------------------------
__global__ __launch_bounds__(256) void softmaxT_kernel() {
    const int m = blockIdx.x * 256 + threadIdx.x;
    float mx = -3.4e38f, sum = 0.f;
    for (int k = 0; k < Kc; k++) {
        float v = g_L[(size_t)k * Mc + m];
        float nm = fmaxf(mx, v);
        sum = sum * __expf(mx - nm) + __expf(v - nm);
        mx = nm;
    }
    const float inv = 1.0f / sum;
    for (int k = 0; k < Kc; k++) {
        size_t o = (size_t)k * Mc + m;
        float p = __expf(g_L[o] - mx) * inv;
        __nv_bfloat16 h = __float2bfloat16(p);
        __nv_bfloat16 l = __float2bfloat16(p - __bfloat162float(h));
        g_St_hi[o] = h;
        g_St_lo[o] = l;
    }
}

// ---------------------------------------------------------------------------
// Kernel 5: GEMM2 — out[b][k][d] = sum_n St[k][b*1024+n] * XT[b][d][n]
// CTA tile 128(k) x 128(d), n-chunks of 32.
// ---------------------------------------------------------------------------
__global__ __launch_bounds__(256) void gemm2_mma(float* __restrict__ out) {
    __shared__ __align__(16) __nv_bfloat16 sm[4 * TILE_ELEMS];
    __nv_bfloat16* sAh = sm;
    __nv_bfloat16* sAl = sm + TILE_ELEMS;
    __nv_bfloat16* sBh = sm + 2 * TILE_ELEMS;
    __nv_bfloat16* sBl = sm + 3 * TILE_ELEMS;

    const int tid = threadIdx.x;
    const int wid = tid >> 5, lane = tid & 31;
    const int d0 = blockIdx.x * 128;
    const int k0 = blockIdx.y * 128;
    const int b  = blockIdx.z;
    const int wm = (wid & 1) * 64;
    const int wn = (wid >> 1) * 32;

    const uint32_t uAh = smem_u32(sAh), uAl = smem_u32(sAl);
    const uint32_t uBh = smem_u32(sBh), uBl = smem_u32(sBl);

    const int a_r = lane & 15;
    const int a_c = (lane & 16) ? 8 : 0;
    const int b_r = lane & 7;
    const int b_c = (lane & 8) ? 8 : 0;
    const uint32_t aoff = (uint32_t)((wm + a_r) * TP + a_c) * 2;
    const uint32_t boff = (uint32_t)((wn + b_r) * TP + b_c) * 2;

    const __nv_bfloat16* Sh = g_St_hi + (size_t)b * Nc;
    const __nv_bfloat16* Sl = g_St_lo + (size_t)b * Nc;
    const __nv_bfloat16* Xh = g_XT_hi + (size_t)b * Dc * Nc;
    const __nv_bfloat16* Xl = g_XT_lo + (size_t)b * Dc * Nc;

    // FIXED load mapping: uint4 = 8 bf16. 128 rows x 32 cols = 512 uint4.
    // lrow in [0,64), lv in {0,8,16,24}; each thread does rows lrow, lrow+64.
    const int lrow = tid >> 2, lv = (tid & 3) * 8;

    float acc[4][4][4] = {};
    uint4 pah[2], pal[2], pbh[2], pbl[2];

    #pragma unroll
    for (int i = 0; i < 2; i++) {
        int row = lrow + 64 * i;
        pah[i] = *(const uint4*)(Sh + (size_t)(k0 + row) * Mc + lv);
        pal[i] = *(const uint4*)(Sl + (size_t)(k0 + row) * Mc + lv);
        pbh[i] = *(const uint4*)(Xh + (size_t)(d0 + row) * Nc + lv);
        pbl[i] = *(const uint4*)(Xl + (size_t)(d0 + row) * Nc + lv);
    }

    for (int c = 0; c < Nc / 32; c++) {
        #pragma unroll
        for (int i = 0; i < 2; i++) {
            int row = lrow + 64 * i;
            *(uint4*)(sAh + row * TP + lv) = pah[i];
            *(uint4*)(sAl + row * TP + lv) = pal[i];
            *(uint4*)(sBh + row * TP + lv) = pbh[i];
            *(uint4*)(sBl + row * TP + lv) = pbl[i];
        }
        __syncthreads();

        if (c + 1 < Nc / 32) {
            int nn = (c + 1) * 32 + lv;
            #pragma unroll
            for (int i = 0; i < 2; i++) {
                int row = lrow + 64 * i;
                pah[i] = *(const uint4*)(Sh + (size_t)(k0 + row) * Mc + nn);
                pal[i] = *(const uint4*)(Sl + (size_t)(k0 + row) * Mc + nn);
                pbh[i] = *(const uint4*)(Xh + (size_t)(d0 + row) * Nc + nn);
                pbl[i] = *(const uint4*)(Xl + (size_t)(d0 + row) * Nc + nn);
            }
        }

        #pragma unroll
        for (int ks = 0; ks < 2; ks++) {
            uint32_t ah[4][4], al[4][4], bh[4][2], bl[4][2];
            #pragma unroll
            for (int mi = 0; mi < 4; mi++) {
                uint32_t off = aoff + (uint32_t)(mi * 16 * TP + ks * 16) * 2;
                ldsm4(ah[mi], uAh + off);
                ldsm4(al[mi], uAl + off);
            }
            #pragma unroll
            for (int ni = 0; ni < 4; ni++) {
                uint32_t off = boff + (uint32_t)(ni * 8 * TP + ks * 16) * 2;
                ldsm2(bh[ni], uBh + off);
                ldsm2(bl[ni], uBl + off);
            }
            #pragma unroll
            for (int mi = 0; mi < 4; mi++)
                #pragma unroll
                for (int ni = 0; ni < 4; ni++) {
                    mma_bf16(acc[mi][ni], ah[mi], bh[ni]);
                    mma_bf16(acc[mi][ni], ah[mi], bl[ni]);
                    mma_bf16(acc[mi][ni], al[mi], bh[ni]);
                }
        }
        __syncthreads();
    }

    float* ob = out + (size_t)b * Kc * Dc;
    #pragma unroll
    for (int mi = 0; mi < 4; mi++) {
        const int kr = k0 + wm + mi * 16 + (lane >> 2);
        #pragma unroll
        for (int ni = 0; ni < 4; ni++) {
            const int dc = d0 + wn + ni * 8 + (lane & 3) * 2;
            float2 o0 = {acc[mi][ni][0], acc[mi][ni][1]};
            float2 o1 = {acc[mi][ni][2], acc[mi][ni][3]};
            *(float2*)(ob + (size_t)kr * Dc + dc) = o0;
            *(float2*)(ob + (size_t)(kr + 8) * Dc + dc) = o1;
        }
    }
}

// ---------------------------------------------------------------------------
extern "C" void kernel_launch(void* const* d_in, const int* in_sizes, int n_in,
                              void* d_out, int out_size) {
    const float* X = (const float*)d_in[0];   // [B,N,D]
    const float* C = (const float*)d_in[1];   // [K,D]
    float* out = (float*)d_out;               // [B,K,D]

    csq_kernel<<<Kc, 256>>>(C);
    convX_kernel<<<dim3(Dc / 32, Nc / 32, Bc), dim3(32, 8)>>>(X);

    gemm1_mma<<<dim3(Kc / 128, Mc / 128), 256>>>(X, C);   // (4, 256)

    softmaxT_kernel<<<Mc / 256, 256>>>();

    gemm2_mma<<<dim3(Dc / 128, Kc / 128, Bc), 256>>>(out); // (6, 4, 32)
}

// round 5
// speedup vs baseline: 2.0426x; 1.2668x over previous
#include <cuda_runtime.h>
#include <cuda_bf16.h>
#include <cstdint>

// ---------------------------------------------------------------------------
// Problem constants
// ---------------------------------------------------------------------------
static constexpr int Bc = 32;
static constexpr int Nc = 1024;
static constexpr int Dc = 768;
static constexpr int Kc = 512;
static constexpr int Mc = Bc * Nc;   // 32768 tokens

// ---------------------------------------------------------------------------
// Global scratch (static __device__ — allocation-guard safe)
// ---------------------------------------------------------------------------
__device__ __align__(16) float         g_L[(size_t)Kc * Mc];      // logits [K][M]
__device__ float                       g_csq[Kc];
__device__ __align__(16) __nv_bfloat16 g_St_hi[(size_t)Kc * Mc];
__device__ __align__(16) __nv_bfloat16 g_St_lo[(size_t)Kc * Mc];
__device__ __align__(16) __nv_bfloat16 g_XT_hi[(size_t)Bc * Dc * Nc];
__device__ __align__(16) __nv_bfloat16 g_XT_lo[(size_t)Bc * Dc * Nc];

// ---------------------------------------------------------------------------
// mma.sync / ldmatrix primitives (baseline sm_80+ PTX)
// ---------------------------------------------------------------------------
__device__ __forceinline__ uint32_t smem_u32(const void* p) {
    uint32_t a;
    asm("{ .reg .u64 t; cvta.to.shared.u64 t, %1; cvt.u32.u64 %0, t; }" : "=r"(a) : "l"(p));
    return a;
}
__device__ __forceinline__ void ldsm4(uint32_t (&r)[4], uint32_t addr) {
    asm volatile("ldmatrix.sync.aligned.m8n8.x4.shared.b16 {%0,%1,%2,%3}, [%4];"
                 : "=r"(r[0]), "=r"(r[1]), "=r"(r[2]), "=r"(r[3]) : "r"(addr));
}
__device__ __forceinline__ void ldsm2(uint32_t (&r)[2], uint32_t addr) {
    asm volatile("ldmatrix.sync.aligned.m8n8.x2.shared.b16 {%0,%1}, [%2];"
                 : "=r"(r[0]), "=r"(r[1]) : "r"(addr));
}
__device__ __forceinline__ void mma_bf16(float (&d)[4], const uint32_t (&a)[4],
                                         const uint32_t (&b)[2]) {
    asm volatile(
        "mma.sync.aligned.m16n8k16.row.col.f32.bf16.bf16.f32 "
        "{%0,%1,%2,%3}, {%4,%5,%6,%7}, {%8,%9}, {%0,%1,%2,%3};"
        : "+f"(d[0]), "+f"(d[1]), "+f"(d[2]), "+f"(d[3])
        : "r"(a[0]), "r"(a[1]), "r"(a[2]), "r"(a[3]), "r"(b[0]), "r"(b[1]));
}

// ---------------------------------------------------------------------------
// Shared tile geometry: 128 rows x 32 bf16 cols, padded stride 40 elems.
// 4 tiles (Ah, Al, Bh, Bl) per buffer, 2 buffers (double-buffered).
// ---------------------------------------------------------------------------
static constexpr int TP = 40;
static constexpr int TILE_ELEMS = 128 * TP;          // 5120
static constexpr int TILEB = TILE_ELEMS * 2;         // 10240 bytes
static constexpr int BUFB  = 4 * TILEB;              // 40960 bytes per buffer
static constexpr int SMEM_GEMM = 2 * BUFB;           // 81920 bytes

__device__ __forceinline__ void cvt_split_store(__nv_bfloat16* hi, __nv_bfloat16* lo,
                                                int eoff, float4 a) {
    float x[4] = {a.x, a.y, a.z, a.w};
    uint32_t hb[4], lb[4];
    #pragma unroll
    for (int i = 0; i < 4; i++) {
        __nv_bfloat16 h = __float2bfloat16(x[i]);
        float r = x[i] - __bfloat162float(h);
        __nv_bfloat16 l = __float2bfloat16(r);
        hb[i] = (uint32_t)__bfloat16_as_ushort(h);
        lb[i] = (uint32_t)__bfloat16_as_ushort(l);
    }
    *(uint2*)(hi + eoff) = make_uint2(hb[0] | (hb[1] << 16), hb[2] | (hb[3] << 16));
    *(uint2*)(lo + eoff) = make_uint2(lb[0] | (lb[1] << 16), lb[2] | (lb[3] << 16));
}

// ---------------------------------------------------------------------------
// Kernel 1: c_sq[k] = sum_d C[k,d]^2
// ---------------------------------------------------------------------------
__global__ void csq_kernel(const float* __restrict__ C) {
    int k = blockIdx.x, t = threadIdx.x;
    const float* row = C + (size_t)k * Dc;
    float s = 0.f;
    for (int d = t; d < Dc; d += 256) { float v = row[d]; s += v * v; }
    #pragma unroll
    for (int o = 16; o > 0; o >>= 1) s += __shfl_xor_sync(0xffffffffu, s, o);
    __shared__ float red[8];
    if ((t & 31) == 0) red[t >> 5] = s;
    __syncthreads();
    if (t == 0) {
        float tot = 0.f;
        #pragma unroll
        for (int w = 0; w < 8; w++) tot += red[w];
        g_csq[k] = tot;
    }
}

// ---------------------------------------------------------------------------
// Kernel 2: convert+transpose X [b][n][d] fp32 -> XT hi/lo bf16 [b][d][n]
// ---------------------------------------------------------------------------
__global__ __launch_bounds__(256) void convX_kernel(const float* __restrict__ X) {
    __shared__ float tile[32][33];
    const int b = blockIdx.z, d0 = blockIdx.x * 32, n0 = blockIdx.y * 32;
    const int tx = threadIdx.x, ty = threadIdx.y;   // (32, 8)
    const float* Xb = X + (size_t)b * Nc * Dc;
    #pragma unroll
    for (int i = 0; i < 4; i++) {
        int r = ty + 8 * i;
        tile[r][tx] = Xb[(size_t)(n0 + r) * Dc + d0 + tx];
    }
    __syncthreads();
    __nv_bfloat16* Hb = g_XT_hi + (size_t)b * Dc * Nc;
    __nv_bfloat16* Lb = g_XT_lo + (size_t)b * Dc * Nc;
    #pragma unroll
    for (int i = 0; i < 4; i++) {
        int rr = ty + 8 * i;
        float v = tile[tx][rr];
        __nv_bfloat16 h = __float2bfloat16(v);
        __nv_bfloat16 l = __float2bfloat16(v - __bfloat162float(h));
        size_t o = (size_t)(d0 + rr) * Nc + n0 + tx;
        Hb[o] = h;
        Lb[o] = l;
    }
}

// ---------------------------------------------------------------------------
// Kernel 3: GEMM1 — Lt[k][m] = 2*<C_k, X_m> - csq[k]
// CTA tile 128(k) x 128(m), d-chunks of 32, double-buffered smem.
// ---------------------------------------------------------------------------
__global__ __launch_bounds__(256) void gemm1_mma(const float* __restrict__ X,
                                                 const float* __restrict__ C) {
    extern __shared__ __align__(16) char dsm[];

    const int tid = threadIdx.x;
    const int wid = tid >> 5, lane = tid & 31;
    const int k0 = blockIdx.x * 128;
    const int m0 = blockIdx.y * 128;
    const int wm = (wid & 1) * 64;
    const int wn = (wid >> 1) * 32;

    const uint32_t ubase = smem_u32(dsm);
    const int a_r = lane & 15;
    const int a_c = (lane & 16) ? 8 : 0;
    const int b_r = lane & 7;
    const int b_c = (lane & 8) ? 8 : 0;
    const uint32_t aoff = (uint32_t)((wm + a_r) * TP + a_c) * 2;
    const uint32_t boff = (uint32_t)((wn + b_r) * TP + b_c) * 2;

    const int lrow = tid >> 3, lv = (tid & 7) * 4;   // 128 rows x 32 cols (float4)
    static constexpr int NCH = Dc / 32;              // 24

    float acc[4][4][4] = {};
    float4 pa[4], pb[4];

    // chunk 0 -> regs -> buffer 0
    #pragma unroll
    for (int i = 0; i < 4; i++) {
        int row = lrow + 32 * i;
        pa[i] = *(const float4*)(C + (size_t)(k0 + row) * Dc + lv);
        pb[i] = *(const float4*)(X + (size_t)(m0 + row) * Dc + lv);
    }
    {
        __nv_bfloat16* bp = (__nv_bfloat16*)(dsm);
        #pragma unroll
        for (int i = 0; i < 4; i++) {
            int row = lrow + 32 * i;
            cvt_split_store(bp, bp + TILE_ELEMS, row * TP + lv, pa[i]);
            cvt_split_store(bp + 2 * TILE_ELEMS, bp + 3 * TILE_ELEMS, row * TP + lv, pb[i]);
        }
    }
    __syncthreads();

    for (int c = 0; c < NCH; c++) {
        const uint32_t cb = (uint32_t)(c & 1) * BUFB;

        if (c + 1 < NCH) {
            int dn = (c + 1) * 32 + lv;
            #pragma unroll
            for (int i = 0; i < 4; i++) {
                int row = lrow + 32 * i;
                pa[i] = *(const float4*)(C + (size_t)(k0 + row) * Dc + dn);
                pb[i] = *(const float4*)(X + (size_t)(m0 + row) * Dc + dn);
            }
        }

        #pragma unroll
        for (int ks = 0; ks < 2; ks++) {
            uint32_t ah[4][4], al[4][4], bh[4][2], bl[4][2];
            #pragma unroll
            for (int mi = 0; mi < 4; mi++) {
                uint32_t off = aoff + (uint32_t)(mi * 16 * TP + ks * 16) * 2;
                ldsm4(ah[mi], ubase + cb + off);
                ldsm4(al[mi], ubase + cb + TILEB + off);
            }
            #pragma unroll
            for (int ni = 0; ni < 4; ni++) {
                uint32_t off = boff + (uint32_t)(ni * 8 * TP + ks * 16) * 2;
                ldsm2(bh[ni], ubase + cb + 2 * TILEB + off);
                ldsm2(bl[ni], ubase + cb + 3 * TILEB + off);
            }
            #pragma unroll
            for (int mi = 0; mi < 4; mi++)
                #pragma unroll
                for (int ni = 0; ni < 4; ni++) {
                    mma_bf16(acc[mi][ni], ah[mi], bh[ni]);
                    mma_bf16(acc[mi][ni], ah[mi], bl[ni]);
                    mma_bf16(acc[mi][ni], al[mi], bh[ni]);
                }
        }

        if (c + 1 < NCH) {
            __nv_bfloat16* bp = (__nv_bfloat16*)(dsm + ((c + 1) & 1) * BUFB);
            #pragma unroll
            for (int i = 0; i < 4; i++) {
                int row = lrow + 32 * i;
                cvt_split_store(bp, bp + TILE_ELEMS, row * TP + lv, pa[i]);
                cvt_split_store(bp + 2 * TILE_ELEMS, bp + 3 * TILE_ELEMS, row * TP + lv, pb[i]);
            }
        }
        __syncthreads();
    }

    #pragma unroll
    for (int mi = 0; mi < 4; mi++) {
        const int kr = k0 + wm + mi * 16 + (lane >> 2);
        const float cs0 = g_csq[kr], cs1 = g_csq[kr + 8];
        #pragma unroll
        for (int ni = 0; ni < 4; ni++) {
            const int mc = m0 + wn + ni * 8 + (lane & 3) * 2;
            float2 o0 = {2.f * acc[mi][ni][0] - cs0, 2.f * acc[mi][ni][1] - cs0};
            float2 o1 = {2.f * acc[mi][ni][2] - cs1, 2.f * acc[mi][ni][3] - cs1};
            *(float2*)(g_L + (size_t)kr * Mc + mc) = o0;
            *(float2*)(g_L + (size_t)(kr + 8) * Mc + mc) = o1;
        }
    }
}

// ---------------------------------------------------------------------------
// Kernel 4: column softmax over k (Lt [Kc][Mc]) -> St hi/lo bf16.
// Block: 64 token-columns (32 lane-pairs) x 8 K-partitions. Grid: Mc/64 = 512.
// ---------------------------------------------------------------------------
__global__ __launch_bounds__(256) void softmaxT_kernel() {
    const int lane = threadIdx.x & 31;   // column pair index
    const int part = threadIdx.x >> 5;   // 0..7 (64 k each)
    const int m0 = blockIdx.x * 64 + lane * 2;
    const float* col = g_L + m0;

    float mx0 = -3.4e38f, mx1 = -3.4e38f, s0 = 0.f, s1 = 0.f;
    const int kb = part * 64;
    #pragma unroll 4
    for (int k = kb; k < kb + 64; k++) {
        float2 v = *(const float2*)(col + (size_t)k * Mc);
        float nm0 = fmaxf(mx0, v.x);
        s0 = s0 * __expf(mx0 - nm0) + __expf(v.x - nm0);
        mx0 = nm0;
        float nm1 = fmaxf(mx1, v.y);
        s1 = s1 * __expf(mx1 - nm1) + __expf(v.y - nm1);
        mx1 = nm1;
    }

    __shared__ float smx[8][64], ssm[8][64];
    smx[part][lane * 2] = mx0;  smx[part][lane * 2 + 1] = mx1;
    ssm[part][lane * 2] = s0;   ssm[part][lane * 2 + 1] = s1;
    __syncthreads();

    float gmx0 = -3.4e38f, gmx1 = -3.4e38f;
    #pragma unroll
    for (int p = 0; p < 8; p++) {
        gmx0 = fmaxf(gmx0, smx[p][lane * 2]);
        gmx1 = fmaxf(gmx1, smx[p][lane * 2 + 1]);
    }
    float gs0 = 0.f, gs1 = 0.f;
    #pragma unroll
    for (int p = 0; p < 8; p++) {
        gs0 += ssm[p][lane * 2]     * __expf(smx[p][lane * 2]     - gmx0);
        gs1 += ssm[p][lane * 2 + 1] * __expf(smx[p][lane * 2 + 1] - gmx1);
    }
    const float inv0 = 1.0f / gs0, inv1 = 1.0f / gs1;

    #pragma unroll 4
    for (int k = kb; k < kb + 64; k++) {
        size_t o = (size_t)k * Mc + m0;
        float2 v = *(const float2*)(g_L + o);
        float p0 = __expf(v.x - gmx0) * inv0;
        float p1 = __expf(v.y - gmx1) * inv1;
        __nv_bfloat16 h0 = __float2bfloat16(p0);
        __nv_bfloat16 l0 = __float2bfloat16(p0 - __bfloat162float(h0));
        __nv_bfloat16 h1 = __float2bfloat16(p1);
        __nv_bfloat16 l1 = __float2bfloat16(p1 - __bfloat162float(h1));
        *(uint32_t*)(g_St_hi + o) =
            (uint32_t)__bfloat16_as_ushort(h0) | ((uint32_t)__bfloat16_as_ushort(h1) << 16);
        *(uint32_t*)(g_St_lo + o) =
            (uint32_t)__bfloat16_as_ushort(l0) | ((uint32_t)__bfloat16_as_ushort(l1) << 16);
    }
}

// ---------------------------------------------------------------------------
// Kernel 5: GEMM2 — out[b][k][d] = sum_n St[k][b*1024+n] * XT[b][d][n]
// CTA tile 128(k) x 128(d), n-chunks of 32, double-buffered smem.
// ---------------------------------------------------------------------------
__global__ __launch_bounds__(256) void gemm2_mma(float* __restrict__ out) {
    extern __shared__ __align__(16) char dsm[];

    const int tid = threadIdx.x;
    const int wid = tid >> 5, lane = tid & 31;
    const int d0 = blockIdx.x * 128;
    const int k0 = blockIdx.y * 128;
    const int b  = blockIdx.z;
    const int wm = (wid & 1) * 64;
    const int wn = (wid >> 1) * 32;

    const uint32_t ubase = smem_u32(dsm);
    const int a_r = lane & 15;
    const int a_c = (lane & 16) ? 8 : 0;
    const int b_r = lane & 7;
    const int b_c = (lane & 8) ? 8 : 0;
    const uint32_t aoff = (uint32_t)((wm + a_r) * TP + a_c) * 2;
    const uint32_t boff = (uint32_t)((wn + b_r) * TP + b_c) * 2;

    const __nv_bfloat16* Sh = g_St_hi + (size_t)b * Nc;
    const __nv_bfloat16* Sl = g_St_lo + (size_t)b * Nc;
    const __nv_bfloat16* Xh = g_XT_hi + (size_t)b * Dc * Nc;
    const __nv_bfloat16* Xl = g_XT_lo + (size_t)b * Dc * Nc;

    // uint4 = 8 bf16; lrow in [0,64), lv in {0,8,16,24}; rows lrow, lrow+64
    const int lrow = tid >> 2, lv = (tid & 3) * 8;
    static constexpr int NCH = Nc / 32;   // 32

    float acc[4][4][4] = {};
    uint4 pah[2], pal[2], pbh[2], pbl[2];

    #pragma unroll
    for (int i = 0; i < 2; i++) {
        int row = lrow + 64 * i;
        pah[i] = *(const uint4*)(Sh + (size_t)(k0 + row) * Mc + lv);
        pal[i] = *(const uint4*)(Sl + (size_t)(k0 + row) * Mc + lv);
        pbh[i] = *(const uint4*)(Xh + (size_t)(d0 + row) * Nc + lv);
        pbl[i] = *(const uint4*)(Xl + (size_t)(d0 + row) * Nc + lv);
    }
    {
        __nv_bfloat16* bp = (__nv_bfloat16*)(dsm);
        #pragma unroll
        for (int i = 0; i < 2; i++) {
            int row = lrow + 64 * i;
            *(uint4*)(bp + row * TP + lv) = pah[i];
            *(uint4*)(bp + TILE_ELEMS + row * TP + lv) = pal[i];
            *(uint4*)(bp + 2 * TILE_ELEMS + row * TP + lv) = pbh[i];
            *(uint4*)(bp + 3 * TILE_ELEMS + row * TP + lv) = pbl[i];
        }
    }
    __syncthreads();

    for (int c = 0; c < NCH; c++) {
        const uint32_t cb = (uint32_t)(c & 1) * BUFB;

        if (c + 1 < NCH) {
            int nn = (c + 1) * 32 + lv;
            #pragma unroll
            for (int i = 0; i < 2; i++) {
                int row = lrow + 64 * i;
                pah[i] = *(const uint4*)(Sh + (size_t)(k0 + row) * Mc + nn);
                pal[i] = *(const uint4*)(Sl + (size_t)(k0 + row) * Mc + nn);
                pbh[i] = *(const uint4*)(Xh + (size_t)(d0 + row) * Nc + nn);
                pbl[i] = *(const uint4*)(Xl + (size_t)(d0 + row) * Nc + nn);
            }
        }

        #pragma unroll
        for (int ks = 0; ks < 2; ks++) {
            uint32_t ah[4][4], al[4][4], bh[4][2], bl[4][2];
            #pragma unroll
            for (int mi = 0; mi < 4; mi++) {
                uint32_t off = aoff + (uint32_t)(mi * 16 * TP + ks * 16) * 2;
                ldsm4(ah[mi], ubase + cb + off);
                ldsm4(al[mi], ubase + cb + TILEB + off);
            }
            #pragma unroll
            for (int ni = 0; ni < 4; ni++) {
                uint32_t off = boff + (uint32_t)(ni * 8 * TP + ks * 16) * 2;
                ldsm2(bh[ni], ubase + cb + 2 * TILEB + off);
                ldsm2(bl[ni], ubase + cb + 3 * TILEB + off);
            }
            #pragma unroll
            for (int mi = 0; mi < 4; mi++)
                #pragma unroll
                for (int ni = 0; ni < 4; ni++) {
                    mma_bf16(acc[mi][ni], ah[mi], bh[ni]);
                    mma_bf16(acc[mi][ni], ah[mi], bl[ni]);
                    mma_bf16(acc[mi][ni], al[mi], bh[ni]);
                }
        }

        if (c + 1 < NCH) {
            __nv_bfloat16* bp = (__nv_bfloat16*)(dsm + ((c + 1) & 1) * BUFB);
            #pragma unroll
            for (int i = 0; i < 2; i++) {
                int row = lrow + 64 * i;
                *(uint4*)(bp + row * TP + lv) = pah[i];
                *(uint4*)(bp + TILE_ELEMS + row * TP + lv) = pal[i];
                *(uint4*)(bp + 2 * TILE_ELEMS + row * TP + lv) = pbh[i];
                *(uint4*)(bp + 3 * TILE_ELEMS + row * TP + lv) = pbl[i];
            }
        }
        __syncthreads();
    }

    float* ob = out + (size_t)b * Kc * Dc;
    #pragma unroll
    for (int mi = 0; mi < 4; mi++) {
        const int kr = k0 + wm + mi * 16 + (lane >> 2);
        #pragma unroll
        for (int ni = 0; ni < 4; ni++) {
            const int dc = d0 + wn + ni * 8 + (lane & 3) * 2;
            float2 o0 = {acc[mi][ni][0], acc[mi][ni][1]};
            float2 o1 = {acc[mi][ni][2], acc[mi][ni][3]};
            *(float2*)(ob + (size_t)kr * Dc + dc) = o0;
            *(float2*)(ob + (size_t)(kr + 8) * Dc + dc) = o1;
        }
    }
}

// ---------------------------------------------------------------------------
extern "C" void kernel_launch(void* const* d_in, const int* in_sizes, int n_in,
                              void* d_out, int out_size) {
    const float* X = (const float*)d_in[0];   // [B,N,D]
    const float* C = (const float*)d_in[1];   // [K,D]
    float* out = (float*)d_out;               // [B,K,D]

    cudaFuncSetAttribute(gemm1_mma, cudaFuncAttributeMaxDynamicSharedMemorySize, SMEM_GEMM);
    cudaFuncSetAttribute(gemm2_mma, cudaFuncAttributeMaxDynamicSharedMemorySize, SMEM_GEMM);

    csq_kernel<<<Kc, 256>>>(C);
    convX_kernel<<<dim3(Dc / 32, Nc / 32, Bc), dim3(32, 8)>>>(X);

    gemm1_mma<<<dim3(Kc / 128, Mc / 128), 256, SMEM_GEMM>>>(X, C);   // (4, 256)

    softmaxT_kernel<<<Mc / 64, 256>>>();                              // 512 blocks

    gemm2_mma<<<dim3(Dc / 128, Kc / 128, Bc), 256, SMEM_GEMM>>>(out); // (6, 4, 32)
}

// round 6
// speedup vs baseline: 2.3517x; 1.1513x over previous
#include <cuda_runtime.h>
#include <cuda_bf16.h>
#include <cstdint>

// ---------------------------------------------------------------------------
// Problem constants
// ---------------------------------------------------------------------------
static constexpr int Bc = 32;
static constexpr int Nc = 1024;
static constexpr int Dc = 768;
static constexpr int Kc = 512;
static constexpr int Mc = Bc * Nc;   // 32768 tokens

// ---------------------------------------------------------------------------
// Global scratch (static __device__ — allocation-guard safe)
// ---------------------------------------------------------------------------
__device__ __align__(16) float         g_L[(size_t)Kc * Mc];        // logits [K][M]
__device__ float                       g_csq[Kc];
__device__ __align__(16) __nv_bfloat16 g_St_hi[(size_t)Kc * Mc];    // probs^T
__device__ __align__(16) __nv_bfloat16 g_St_lo[(size_t)Kc * Mc];
__device__ __align__(16) __nv_bfloat16 g_XT_hi[(size_t)Bc * Dc * Nc]; // X^T [b][d][n]
__device__ __align__(16) __nv_bfloat16 g_XT_lo[(size_t)Bc * Dc * Nc];
__device__ __align__(16) __nv_bfloat16 g_Xd_hi[(size_t)Mc * Dc];    // X [m][d] split
__device__ __align__(16) __nv_bfloat16 g_Xd_lo[(size_t)Mc * Dc];
__device__ __align__(16) __nv_bfloat16 g_C_hi[(size_t)Kc * Dc];     // C [k][d] split
__device__ __align__(16) __nv_bfloat16 g_C_lo[(size_t)Kc * Dc];

// ---------------------------------------------------------------------------
// Primitives (baseline sm_80+ PTX — valid on plain sm_103 target)
// ---------------------------------------------------------------------------
__device__ __forceinline__ uint32_t smem_u32(const void* p) {
    uint32_t a;
    asm("{ .reg .u64 t; cvta.to.shared.u64 t, %1; cvt.u32.u64 %0, t; }" : "=r"(a) : "l"(p));
    return a;
}
__device__ __forceinline__ void ldsm4(uint32_t (&r)[4], uint32_t addr) {
    asm volatile("ldmatrix.sync.aligned.m8n8.x4.shared.b16 {%0,%1,%2,%3}, [%4];"
                 : "=r"(r[0]), "=r"(r[1]), "=r"(r[2]), "=r"(r[3]) : "r"(addr));
}
__device__ __forceinline__ void ldsm2(uint32_t (&r)[2], uint32_t addr) {
    asm volatile("ldmatrix.sync.aligned.m8n8.x2.shared.b16 {%0,%1}, [%2];"
                 : "=r"(r[0]), "=r"(r[1]) : "r"(addr));
}
__device__ __forceinline__ void mma_bf16(float (&d)[4], const uint32_t (&a)[4],
                                         const uint32_t (&b)[2]) {
    asm volatile(
        "mma.sync.aligned.m16n8k16.row.col.f32.bf16.bf16.f32 "
        "{%0,%1,%2,%3}, {%4,%5,%6,%7}, {%8,%9}, {%0,%1,%2,%3};"
        : "+f"(d[0]), "+f"(d[1]), "+f"(d[2]), "+f"(d[3])
        : "r"(a[0]), "r"(a[1]), "r"(a[2]), "r"(a[3]), "r"(b[0]), "r"(b[1]));
}
__device__ __forceinline__ void cp16(uint32_t saddr, const void* g) {
    asm volatile("cp.async.cg.shared.global [%0], [%1], 16;" :: "r"(saddr), "l"(g));
}
#define CP_COMMIT() asm volatile("cp.async.commit_group;" ::: "memory")
#define CP_WAIT1()  asm volatile("cp.async.wait_group 1;" ::: "memory")

// ---------------------------------------------------------------------------
// Shared tile geometry: 128 rows x 32 bf16 cols, padded stride 40 elems.
// 4 tiles (Ah, Al, Bh, Bl) per buffer, 2 buffers.
// ---------------------------------------------------------------------------
static constexpr int TP = 40;
static constexpr int TILE_ELEMS = 128 * TP;          // 5120
static constexpr int TILEB = TILE_ELEMS * 2;         // 10240 bytes
static constexpr int BUFB  = 4 * TILEB;              // 40960 bytes per buffer
static constexpr int SMEM_GEMM = 2 * BUFB;           // 81920 bytes

// ---------------------------------------------------------------------------
// Kernel 1: c_sq[k] = sum_d C[k,d]^2
// ---------------------------------------------------------------------------
__global__ void csq_kernel(const float* __restrict__ C) {
    int k = blockIdx.x, t = threadIdx.x;
    const float* row = C + (size_t)k * Dc;
    float s = 0.f;
    for (int d = t; d < Dc; d += 256) { float v = row[d]; s += v * v; }
    #pragma unroll
    for (int o = 16; o > 0; o >>= 1) s += __shfl_xor_sync(0xffffffffu, s, o);
    __shared__ float red[8];
    if ((t & 31) == 0) red[t >> 5] = s;
    __syncthreads();
    if (t == 0) {
        float tot = 0.f;
        #pragma unroll
        for (int w = 0; w < 8; w++) tot += red[w];
        g_csq[k] = tot;
    }
}

// ---------------------------------------------------------------------------
// Kernel 2: streaming fp32 -> hi/lo bf16 split (no transpose)
// ---------------------------------------------------------------------------
__global__ __launch_bounds__(256) void split_kernel(const float* __restrict__ src,
                                                    __nv_bfloat16* __restrict__ h,
                                                    __nv_bfloat16* __restrict__ l) {
    size_t i = ((size_t)blockIdx.x * 256 + threadIdx.x) * 4;
    float4 v = *(const float4*)(src + i);
    float x[4] = {v.x, v.y, v.z, v.w};
    uint32_t hb[4], lb[4];
    #pragma unroll
    for (int j = 0; j < 4; j++) {
        __nv_bfloat16 hh = __float2bfloat16(x[j]);
        float r = x[j] - __bfloat162float(hh);
        __nv_bfloat16 ll = __float2bfloat16(r);
        hb[j] = (uint32_t)__bfloat16_as_ushort(hh);
        lb[j] = (uint32_t)__bfloat16_as_ushort(ll);
    }
    *(uint2*)(h + i) = make_uint2(hb[0] | (hb[1] << 16), hb[2] | (hb[3] << 16));
    *(uint2*)(l + i) = make_uint2(lb[0] | (lb[1] << 16), lb[2] | (lb[3] << 16));
}

// ---------------------------------------------------------------------------
// Kernel 3: convert+transpose X [b][n][d] fp32 -> XT hi/lo bf16 [b][d][n]
// ---------------------------------------------------------------------------
__global__ __launch_bounds__(256) void convX_kernel(const float* __restrict__ X) {
    __shared__ float tile[32][33];
    const int b = blockIdx.z, d0 = blockIdx.x * 32, n0 = blockIdx.y * 32;
    const int tx = threadIdx.x, ty = threadIdx.y;   // (32, 8)
    const float* Xb = X + (size_t)b * Nc * Dc;
    #pragma unroll
    for (int i = 0; i < 4; i++) {
        int r = ty + 8 * i;
        tile[r][tx] = Xb[(size_t)(n0 + r) * Dc + d0 + tx];
    }
    __syncthreads();
    __nv_bfloat16* Hb = g_XT_hi + (size_t)b * Dc * Nc;
    __nv_bfloat16* Lb = g_XT_lo + (size_t)b * Dc * Nc;
    #pragma unroll
    for (int i = 0; i < 4; i++) {
        int rr = ty + 8 * i;
        float v = tile[tx][rr];
        __nv_bfloat16 h = __float2bfloat16(v);
        __nv_bfloat16 l = __float2bfloat16(v - __bfloat162float(h));
        size_t o = (size_t)(d0 + rr) * Nc + n0 + tx;
        Hb[o] = h;
        Lb[o] = l;
    }
}

// ---------------------------------------------------------------------------
// Shared MMA compute phase (identical fragment layout in both GEMMs)
// ---------------------------------------------------------------------------
struct Frag { float acc[4][4][4]; };

__device__ __forceinline__ void mma_chunk(float (&acc)[4][4][4], uint32_t ubase,
                                          uint32_t cb, uint32_t aoff, uint32_t boff) {
    #pragma unroll
    for (int ks = 0; ks < 2; ks++) {
        uint32_t ah[4][4], al[4][4], bh[4][2], bl[4][2];
        #pragma unroll
        for (int mi = 0; mi < 4; mi++) {
            uint32_t off = aoff + (uint32_t)(mi * 16 * TP + ks * 16) * 2;
            ldsm4(ah[mi], ubase + cb + off);
            ldsm4(al[mi], ubase + cb + TILEB + off);
        }
        #pragma unroll
        for (int ni = 0; ni < 4; ni++) {
            uint32_t off = boff + (uint32_t)(ni * 8 * TP + ks * 16) * 2;
            ldsm2(bh[ni], ubase + cb + 2 * TILEB + off);
            ldsm2(bl[ni], ubase + cb + 3 * TILEB + off);
        }
        #pragma unroll
        for (int mi = 0; mi < 4; mi++)
            #pragma unroll
            for (int ni = 0; ni < 4; ni++) {
                mma_bf16(acc[mi][ni], ah[mi], bh[ni]);
                mma_bf16(acc[mi][ni], ah[mi], bl[ni]);
                mma_bf16(acc[mi][ni], al[mi], bh[ni]);
            }
    }
}

// ---------------------------------------------------------------------------
// Kernel 4: GEMM1 — Lt[k][m] = 2*<C_k, X_m> - csq[k]
// A = C hi/lo [k][d], B = Xd hi/lo [m][d]; all bf16, cp.async pipeline.
// ---------------------------------------------------------------------------
__global__ __launch_bounds__(256) void gemm1_mma() {
    extern __shared__ __align__(16) char dsm[];
    const int tid = threadIdx.x;
    const int wid = tid >> 5, lane = tid & 31;
    const int k0 = blockIdx.x * 128;
    const int m0 = blockIdx.y * 128;
    const int wm = (wid & 1) * 64;
    const int wn = (wid >> 1) * 32;

    const uint32_t ubase = smem_u32(dsm);
    const int a_r = lane & 15;
    const int a_c = (lane & 16) ? 8 : 0;
    const int b_r = lane & 7;
    const int b_c = (lane & 8) ? 8 : 0;
    const uint32_t aoff = (uint32_t)((wm + a_r) * TP + a_c) * 2;
    const uint32_t boff = (uint32_t)((wn + b_r) * TP + b_c) * 2;

    const int lrow = tid >> 2, lv = (tid & 3) * 8;   // rows lrow, lrow+64; 8 bf16
    static constexpr int NCH = Dc / 32;              // 24

    float acc[4][4][4] = {};

    auto issue = [&](int c, uint32_t buf) {
        const int db = c * 32 + lv;
        #pragma unroll
        for (int i = 0; i < 2; i++) {
            int row = lrow + 64 * i;
            uint32_t so = buf + (uint32_t)(row * TP + lv) * 2;
            cp16(ubase + so,             g_C_hi  + (size_t)(k0 + row) * Dc + db);
            cp16(ubase + so + TILEB,     g_C_lo  + (size_t)(k0 + row) * Dc + db);
            cp16(ubase + so + 2 * TILEB, g_Xd_hi + (size_t)(m0 + row) * Dc + db);
            cp16(ubase + so + 3 * TILEB, g_Xd_lo + (size_t)(m0 + row) * Dc + db);
        }
    };

    issue(0, 0);
    CP_COMMIT();
    for (int c = 0; c < NCH; c++) {
        if (c + 1 < NCH) issue(c + 1, (uint32_t)((c + 1) & 1) * BUFB);
        CP_COMMIT();
        CP_WAIT1();
        __syncthreads();
        mma_chunk(acc, ubase, (uint32_t)(c & 1) * BUFB, aoff, boff);
        __syncthreads();
    }

    #pragma unroll
    for (int mi = 0; mi < 4; mi++) {
        const int kr = k0 + wm + mi * 16 + (lane >> 2);
        const float cs0 = g_csq[kr], cs1 = g_csq[kr + 8];
        #pragma unroll
        for (int ni = 0; ni < 4; ni++) {
            const int mc = m0 + wn + ni * 8 + (lane & 3) * 2;
            float2 o0 = {2.f * acc[mi][ni][0] - cs0, 2.f * acc[mi][ni][1] - cs0};
            float2 o1 = {2.f * acc[mi][ni][2] - cs1, 2.f * acc[mi][ni][3] - cs1};
            *(float2*)(g_L + (size_t)kr * Mc + mc) = o0;
            *(float2*)(g_L + (size_t)(kr + 8) * Mc + mc) = o1;
        }
    }
}

// ---------------------------------------------------------------------------
// Kernel 5: column softmax over k (Lt [Kc][Mc]) -> St hi/lo bf16.
// ---------------------------------------------------------------------------
__global__ __launch_bounds__(256) void softmaxT_kernel() {
    const int lane = threadIdx.x & 31;
    const int part = threadIdx.x >> 5;
    const int m0 = blockIdx.x * 64 + lane * 2;
    const float* col = g_L + m0;

    float mx0 = -3.4e38f, mx1 = -3.4e38f, s0 = 0.f, s1 = 0.f;
    const int kb = part * 64;
    #pragma unroll 4
    for (int k = kb; k < kb + 64; k++) {
        float2 v = *(const float2*)(col + (size_t)k * Mc);
        float nm0 = fmaxf(mx0, v.x);
        s0 = s0 * __expf(mx0 - nm0) + __expf(v.x - nm0);
        mx0 = nm0;
        float nm1 = fmaxf(mx1, v.y);
        s1 = s1 * __expf(mx1 - nm1) + __expf(v.y - nm1);
        mx1 = nm1;
    }

    __shared__ float smx[8][64], ssm[8][64];
    smx[part][lane * 2] = mx0;  smx[part][lane * 2 + 1] = mx1;
    ssm[part][lane * 2] = s0;   ssm[part][lane * 2 + 1] = s1;
    __syncthreads();

    float gmx0 = -3.4e38f, gmx1 = -3.4e38f;
    #pragma unroll
    for (int p = 0; p < 8; p++) {
        gmx0 = fmaxf(gmx0, smx[p][lane * 2]);
        gmx1 = fmaxf(gmx1, smx[p][lane * 2 + 1]);
    }
    float gs0 = 0.f, gs1 = 0.f;
    #pragma unroll
    for (int p = 0; p < 8; p++) {
        gs0 += ssm[p][lane * 2]     * __expf(smx[p][lane * 2]     - gmx0);
        gs1 += ssm[p][lane * 2 + 1] * __expf(smx[p][lane * 2 + 1] - gmx1);
    }
    const float inv0 = 1.0f / gs0, inv1 = 1.0f / gs1;

    #pragma unroll 4
    for (int k = kb; k < kb + 64; k++) {
        size_t o = (size_t)k * Mc + m0;
        float2 v = *(const float2*)(g_L + o);
        float p0 = __expf(v.x - gmx0) * inv0;
        float p1 = __expf(v.y - gmx1) * inv1;
        __nv_bfloat16 h0 = __float2bfloat16(p0);
        __nv_bfloat16 l0 = __float2bfloat16(p0 - __bfloat162float(h0));
        __nv_bfloat16 h1 = __float2bfloat16(p1);
        __nv_bfloat16 l1 = __float2bfloat16(p1 - __bfloat162float(h1));
        *(uint32_t*)(g_St_hi + o) =
            (uint32_t)__bfloat16_as_ushort(h0) | ((uint32_t)__bfloat16_as_ushort(h1) << 16);
        *(uint32_t*)(g_St_lo + o) =
            (uint32_t)__bfloat16_as_ushort(l0) | ((uint32_t)__bfloat16_as_ushort(l1) << 16);
    }
}

// ---------------------------------------------------------------------------
// Kernel 6: GEMM2 — out[b][k][d] = sum_n St[k][b*1024+n] * XT[b][d][n]
// ---------------------------------------------------------------------------
__global__ __launch_bounds__(256) void gemm2_mma(float* __restrict__ out) {
    extern __shared__ __align__(16) char dsm[];
    const int tid = threadIdx.x;
    const int wid = tid >> 5, lane = tid & 31;
    const int d0 = blockIdx.x * 128;
    const int k0 = blockIdx.y * 128;
    const int b  = blockIdx.z;
    const int wm = (wid & 1) * 64;
    const int wn = (wid >> 1) * 32;

    const uint32_t ubase = smem_u32(dsm);
    const int a_r = lane & 15;
    const int a_c = (lane & 16) ? 8 : 0;
    const int b_r = lane & 7;
    const int b_c = (lane & 8) ? 8 : 0;
    const uint32_t aoff = (uint32_t)((wm + a_r) * TP + a_c) * 2;
    const uint32_t boff = (uint32_t)((wn + b_r) * TP + b_c) * 2;

    const __nv_bfloat16* Sh = g_St_hi + (size_t)b * Nc;
    const __nv_bfloat16* Sl = g_St_lo + (size_t)b * Nc;
    const __nv_bfloat16* Xh = g_XT_hi + (size_t)b * Dc * Nc;
    const __nv_bfloat16* Xl = g_XT_lo + (size_t)b * Dc * Nc;

    const int lrow = tid >> 2, lv = (tid & 3) * 8;
    static constexpr int NCH = Nc / 32;   // 32

    float acc[4][4][4] = {};

    auto issue = [&](int c, uint32_t buf) {
        const int nb = c * 32 + lv;
        #pragma unroll
        for (int i = 0; i < 2; i++) {
            int row = lrow + 64 * i;
            uint32_t so = buf + (uint32_t)(row * TP + lv) * 2;
            cp16(ubase + so,             Sh + (size_t)(k0 + row) * Mc + nb);
            cp16(ubase + so + TILEB,     Sl + (size_t)(k0 + row) * Mc + nb);
            cp16(ubase + so + 2 * TILEB, Xh + (size_t)(d0 + row) * Nc + nb);
            cp16(ubase + so + 3 * TILEB, Xl + (size_t)(d0 + row) * Nc + nb);
        }
    };

    issue(0, 0);
    CP_COMMIT();
    for (int c = 0; c < NCH; c++) {
        if (c + 1 < NCH) issue(c + 1, (uint32_t)((c + 1) & 1) * BUFB);
        CP_COMMIT();
        CP_WAIT1();
        __syncthreads();
        mma_chunk(acc, ubase, (uint32_t)(c & 1) * BUFB, aoff, boff);
        __syncthreads();
    }

    float* ob = out + (size_t)b * Kc * Dc;
    #pragma unroll
    for (int mi = 0; mi < 4; mi++) {
        const int kr = k0 + wm + mi * 16 + (lane >> 2);
        #pragma unroll
        for (int ni = 0; ni < 4; ni++) {
            const int dc = d0 + wn + ni * 8 + (lane & 3) * 2;
            float2 o0 = {acc[mi][ni][0], acc[mi][ni][1]};
            float2 o1 = {acc[mi][ni][2], acc[mi][ni][3]};
            *(float2*)(ob + (size_t)kr * Dc + dc) = o0;
            *(float2*)(ob + (size_t)(kr + 8) * Dc + dc) = o1;
        }
    }
}

// ---------------------------------------------------------------------------
extern "C" void kernel_launch(void* const* d_in, const int* in_sizes, int n_in,
                              void* d_out, int out_size) {
    const float* X = (const float*)d_in[0];   // [B,N,D]
    const float* C = (const float*)d_in[1];   // [K,D]
    float* out = (float*)d_out;               // [B,K,D]

    cudaFuncSetAttribute(gemm1_mma, cudaFuncAttributeMaxDynamicSharedMemorySize, SMEM_GEMM);
    cudaFuncSetAttribute(gemm2_mma, cudaFuncAttributeMaxDynamicSharedMemorySize, SMEM_GEMM);

    __nv_bfloat16 *xd_h, *xd_l, *c_h, *c_l;
    cudaGetSymbolAddress((void**)&xd_h, g_Xd_hi);
    cudaGetSymbolAddress((void**)&xd_l, g_Xd_lo);
    cudaGetSymbolAddress((void**)&c_h,  g_C_hi);
    cudaGetSymbolAddress((void**)&c_l,  g_C_lo);

    csq_kernel<<<Kc, 256>>>(C);
    split_kernel<<<(int)(((size_t)Mc * Dc / 4) / 256), 256>>>(X, xd_h, xd_l);
    split_kernel<<<(int)(((size_t)Kc * Dc / 4) / 256), 256>>>(C, c_h, c_l);
    convX_kernel<<<dim3(Dc / 32, Nc / 32, Bc), dim3(32, 8)>>>(X);

    gemm1_mma<<<dim3(Kc / 128, Mc / 128), 256, SMEM_GEMM>>>();        // (4, 256)

    softmaxT_kernel<<<Mc / 64, 256>>>();                              // 512 blocks

    gemm2_mma<<<dim3(Dc / 128, Kc / 128, Bc), 256, SMEM_GEMM>>>(out); // (6, 4, 32)
}